// round 10
// baseline (speedup 1.0000x reference)
#include <cuda_runtime.h>
#include <cuda_fp16.h>
#include <cuda_bf16.h>
#include <stdint.h>

// Problem constants (fixed by the dataset).
#define N_NODES 65536
#define N_EDGES 1048576
#define D 64

#define GEMM_BLOCKS    (N_NODES / 128)        // 512
#define DEG_BLOCKS     (N_EDGES / 4 / 256)    // 1024
#define REORDER_BLOCKS (N_EDGES / 256)        // 4096
#define SCALE_BLOCKS   (N_NODES * 16 / 256)   // 4096

// Scratch: __device__ globals (no allocation allowed in kernel_launch).
__device__ __align__(16) float  g_h[N_NODES * D];    // h = x @ W, fp32 (16 MB)
__device__ __align__(16) __half g_h16[N_NODES * D];  // h*dinv in fp16 (8 MB)
__device__ float g_dinv[N_NODES];                    // rsqrt(deg+1)
__device__ int   g_deg[N_NODES];                     // in-degree w/o self-loop
__device__ int   g_row_start[N_NODES + 1];           // CSR offsets (by dst)
__device__ int   g_cursor[N_NODES];                  // fill cursors
__device__ int   g_csr_src[N_EDGES];                 // src per CSR slot

// ---------------------------------------------------------------------------
// Stage 1 (hetero): blocks [0,512) GEMM mainloop h = x @ W -> g_h;
// blocks [512,1536) degree count (hidden under the GEMM).
__global__ __launch_bounds__(256) void k_fused(const float* __restrict__ x,
                                               const float* __restrict__ W,
                                               const int* __restrict__ ei) {
    __shared__ __align__(16) float xs[64 * 128];
    __shared__ __align__(16) float ws[64 * 64];

    const int tid = threadIdx.x;

    if (blockIdx.x >= GEMM_BLOCKS) {
        int t = (blockIdx.x - GEMM_BLOCKS) * 256 + tid;
        int4 d = ((const int4*)(ei + N_EDGES))[t];
        atomicAdd(&g_deg[d.x], 1);
        atomicAdd(&g_deg[d.y], 1);
        atomicAdd(&g_deg[d.z], 1);
        atomicAdd(&g_deg[d.w], 1);
        return;
    }

    const int rowBase = blockIdx.x * 128;
    {
        const float4* Wv = (const float4*)W;
        float4* wsv = (float4*)ws;
        #pragma unroll
        for (int q = 0; q < 4; q++) wsv[tid + q * 256] = Wv[tid + q * 256];
    }
    {
        int row = tid & 127;
        int kq  = tid >> 7;
        const float4* xrow = (const float4*)&x[(size_t)(rowBase + row) * D];
        #pragma unroll
        for (int q = 0; q < 8; q++) {
            int k0 = kq * 32 + q * 4;
            float4 v = xrow[k0 >> 2];
            xs[(k0 + 0) * 128 + row] = v.x;
            xs[(k0 + 1) * 128 + row] = v.y;
            xs[(k0 + 2) * 128 + row] = v.z;
            xs[(k0 + 3) * 128 + row] = v.w;
        }
    }
    __syncthreads();

    const int ty = tid >> 4;
    const int tx = tid & 15;

    float acc[8][4] = {};
    #pragma unroll 8
    for (int k = 0; k < 64; k++) {
        float4 a0 = *(const float4*)&xs[k * 128 + ty * 8];
        float4 a1 = *(const float4*)&xs[k * 128 + ty * 8 + 4];
        float4 w4 = *(const float4*)&ws[k * 64 + tx * 4];
        float av[8] = {a0.x, a0.y, a0.z, a0.w, a1.x, a1.y, a1.z, a1.w};
        #pragma unroll
        for (int i = 0; i < 8; i++) {
            acc[i][0] += av[i] * w4.x;
            acc[i][1] += av[i] * w4.y;
            acc[i][2] += av[i] * w4.z;
            acc[i][3] += av[i] * w4.w;
        }
    }
    #pragma unroll
    for (int i = 0; i < 8; i++) {
        int r = rowBase + ty * 8 + i;
        *(float4*)&g_h[(size_t)r * D + tx * 4] =
            make_float4(acc[i][0], acc[i][1], acc[i][2], acc[i][3]);
    }
}

// ---------------------------------------------------------------------------
// Stage 2: exclusive scan of in-degree -> CSR row offsets + cursors.
// Single block, 1024 threads, 64 nodes per thread.
__global__ __launch_bounds__(1024) void k_scan() {
    __shared__ int chunk[1024];
    const int tid = threadIdx.x;
    const int base = tid * 64;

    int s = 0;
    #pragma unroll
    for (int i = 0; i < 64; i++) s += g_deg[base + i];
    chunk[tid] = s;
    __syncthreads();

    for (int off = 1; off < 1024; off <<= 1) {
        int u = (tid >= off) ? chunk[tid - off] : 0;
        __syncthreads();
        chunk[tid] += u;
        __syncthreads();
    }
    int run = chunk[tid] - s;  // exclusive base

    for (int i = 0; i < 64; i++) {
        int n = base + i;
        g_row_start[n] = run;
        g_cursor[n] = run;
        run += g_deg[n];
    }
    if (tid == 1023) g_row_start[N_NODES] = run;  // == N_EDGES
}

// ---------------------------------------------------------------------------
// Stage 3 (hetero): blocks [0,4096) reorder edges into CSR by dst;
// blocks [4096,8192) scale: dinv = rsqrt(deg+1); g_h16 = half(h * dinv).
// The two phases are independent (reorder: edges+cursors; scale: deg+h).
__global__ __launch_bounds__(256) void k_prep(const int* __restrict__ ei) {
    const int tid = threadIdx.x;
    if (blockIdx.x < REORDER_BLOCKS) {
        int e = blockIdx.x * 256 + tid;
        int src = ei[e];
        int dst = ei[N_EDGES + e];
        int pos = atomicAdd(&g_cursor[dst], 1);
        g_csr_src[pos] = src;
    } else {
        int t = (blockIdx.x - REORDER_BLOCKS) * 256 + tid;
        int node = t >> 4;
        int j4   = (t & 15) * 4;
        float di = rsqrtf((float)(g_deg[node] + 1));
        if ((t & 15) == 0) g_dinv[node] = di;
        float4 hv = *(const float4*)&g_h[(size_t)node * D + j4];
        union { __half2 h2[2]; uint2 u; } pk;
        pk.h2[0] = __floats2half2_rn(hv.x * di, hv.y * di);
        pk.h2[1] = __floats2half2_rn(hv.z * di, hv.w * di);
        *(uint2*)&g_h16[(size_t)node * D + j4] = pk.u;
    }
}

// ---------------------------------------------------------------------------
// Stage 4: pull aggregation, warp per node. Lane owns 2 features.
// Neighbor indices are broadcast loads (all lanes, same address); h16-row
// gathers are coalesced 128B per warp, unroll-4 for MLP. Zero atomics.
//   out[i] = b + dinv_i * sum_s h16[s] + dinv_i^2 * h[i]
__global__ __launch_bounds__(256) void k_pull(const float* __restrict__ b,
                                              float* __restrict__ out) {
    const int warp = (blockIdx.x * 256 + threadIdx.x) >> 5;
    const int lane = threadIdx.x & 31;
    const int node = warp;

    int beg = g_row_start[node];
    int end = g_row_start[node + 1];

    float2 acc = make_float2(0.f, 0.f);
    #pragma unroll 4
    for (int k = beg; k < end; k++) {
        int s = g_csr_src[k];  // broadcast within warp
        uint32_t raw = *(const uint32_t*)&g_h16[(size_t)s * D + lane * 2];
        float2 f = __half22float2(*(__half2*)&raw);
        acc.x += f.x;
        acc.y += f.y;
    }

    float di = g_dinv[node];
    float s2 = di * di;
    float2 hv = *(const float2*)&g_h[(size_t)node * D + lane * 2];
    float2 bv = *(const float2*)&b[lane * 2];
    float2 ov = make_float2(bv.x + di * acc.x + s2 * hv.x,
                            bv.y + di * acc.y + s2 * hv.y);
    *(float2*)&out[(size_t)node * D + lane * 2] = ov;
}

// ---------------------------------------------------------------------------
extern "C" void kernel_launch(void* const* d_in, const int* in_sizes, int n_in,
                              void* d_out, int out_size) {
    const float* x  = (const float*)d_in[0];
    const int*   ei = (const int*)d_in[1];    // [2, E] int32
    const float* W  = (const float*)d_in[2];
    const float* b  = (const float*)d_in[3];
    float* out = (float*)d_out;

    (void)in_sizes; (void)n_in; (void)out_size;

    void* deg_ptr = nullptr;
    cudaGetSymbolAddress(&deg_ptr, g_deg);
    cudaMemsetAsync(deg_ptr, 0, N_NODES * sizeof(int));

    k_fused<<<GEMM_BLOCKS + DEG_BLOCKS, 256>>>(x, W, ei);
    k_scan<<<1, 1024>>>();
    k_prep<<<REORDER_BLOCKS + SCALE_BLOCKS, 256>>>(ei);
    k_pull<<<N_NODES / 8, 256>>>(b, out);
}

// round 12
// speedup vs baseline: 2.7707x; 2.7707x over previous
#include <cuda_runtime.h>
#include <cuda_bf16.h>
#include <stdint.h>

// Problem constants (fixed by the dataset).
#define N_NODES 65536
#define N_EDGES 1048576
#define D 64

#define GEMM_BLOCKS (N_NODES / 256)            // 256 (256-row tiles)
#define DEG_BLOCKS  (N_EDGES / 4 / 256)        // 1024
#define FUSED_SMEM  ((256 * 64 + 64 * 64) * 4) // 80 KB dynamic

// Scratch: __device__ globals (no allocation allowed in kernel_launch).
__device__ __align__(16) float g_h[N_NODES * D];  // h = x @ W (16 MB)
__device__ float g_dinv[N_NODES];                 // rsqrt(deg+1)
__device__ int   g_deg[N_NODES];                  // in-degree w/o self-loop

// ---------------------------------------------------------------------------
// Fused kernel: blocks [0,256) run the GEMM (256-row tile, 8x8 micro-tile);
// blocks [256,1280) run the degree count (hidden under the GEMM).
__global__ __launch_bounds__(256) void k_fused(const float* __restrict__ x,
                                               const float* __restrict__ W,
                                               const int* __restrict__ ei) {
    extern __shared__ __align__(16) float smem[];
    float* xs = smem;              // [64][256] transposed: xs[k*256 + row]
    float* ws = smem + 256 * 64;   // [64][64]  row-major:  ws[k*64 + j]

    const int tid = threadIdx.x;

    if (blockIdx.x >= GEMM_BLOCKS) {
        // ---- degree-count phase: 4 edges per thread via int4 ----
        int t = (blockIdx.x - GEMM_BLOCKS) * 256 + tid;
        int4 d = ((const int4*)(ei + N_EDGES))[t];
        atomicAdd(&g_deg[d.x], 1);
        atomicAdd(&g_deg[d.y], 1);
        atomicAdd(&g_deg[d.z], 1);
        atomicAdd(&g_deg[d.w], 1);
        return;
    }

    // ---- GEMM phase ----
    const int rowBase = blockIdx.x * 256;

    // Load W: 1024 float4, 4 per thread.
    {
        const float4* Wv = (const float4*)W;
        float4* wsv = (float4*)ws;
        #pragma unroll
        for (int q = 0; q < 4; q++) wsv[tid + q * 256] = Wv[tid + q * 256];
    }
    // Load x tile transposed: thread loads row tid (16 float4 along k).
    {
        int row = tid;
        const float4* xrow = (const float4*)&x[(size_t)(rowBase + row) * D];
        #pragma unroll
        for (int q = 0; q < 16; q++) {
            int k0 = q * 4;
            float4 v = xrow[q];
            xs[(k0 + 0) * 256 + row] = v.x;
            xs[(k0 + 1) * 256 + row] = v.y;
            xs[(k0 + 2) * 256 + row] = v.z;
            xs[(k0 + 3) * 256 + row] = v.w;
        }
    }
    __syncthreads();

    const int ty = tid >> 3;   // 0..31 -> rows ty*8 .. ty*8+7
    const int tx = tid & 7;    // 0..7  -> cols tx*8 .. tx*8+7

    float acc[8][8] = {};
    #pragma unroll 8
    for (int k = 0; k < 64; k++) {
        float4 a0 = *(const float4*)&xs[k * 256 + ty * 8];
        float4 a1 = *(const float4*)&xs[k * 256 + ty * 8 + 4];
        float4 w0 = *(const float4*)&ws[k * 64 + tx * 8];
        float4 w1 = *(const float4*)&ws[k * 64 + tx * 8 + 4];
        float av[8] = {a0.x, a0.y, a0.z, a0.w, a1.x, a1.y, a1.z, a1.w};
        float wv[8] = {w0.x, w0.y, w0.z, w0.w, w1.x, w1.y, w1.z, w1.w};
        #pragma unroll
        for (int i = 0; i < 8; i++)
            #pragma unroll
            for (int j = 0; j < 8; j++)
                acc[i][j] += av[i] * wv[j];
    }

    #pragma unroll
    for (int i = 0; i < 8; i++) {
        int r = rowBase + ty * 8 + i;
        *(float4*)&g_h[(size_t)r * D + tx * 8] =
            make_float4(acc[i][0], acc[i][1], acc[i][2], acc[i][3]);
        *(float4*)&g_h[(size_t)r * D + tx * 8 + 4] =
            make_float4(acc[i][4], acc[i][5], acc[i][6], acc[i][7]);
    }
}

// ---------------------------------------------------------------------------
// Finish kernel: dinv = rsqrt(deg+1); out = h*dinv^2 + b (self-loop + bias).
__global__ __launch_bounds__(256) void k_finish(const float* __restrict__ b,
                                                float* __restrict__ out) {
    int t = blockIdx.x * blockDim.x + threadIdx.x;
    int node = t >> 4;
    int j4   = (t & 15) * 4;

    float di = rsqrtf((float)(g_deg[node] + 1));
    if ((t & 15) == 0) g_dinv[node] = di;
    float s = di * di;

    float4 hv = *(const float4*)&g_h[(size_t)node * D + j4];
    float4 bv = *(const float4*)&b[j4];
    *(float4*)&out[(size_t)node * D + j4] =
        make_float4(hv.x * s + bv.x, hv.y * s + bv.y,
                    hv.z * s + bv.z, hv.w * s + bv.w);
}

// ---------------------------------------------------------------------------
// Edge scatter (R8-proven, atomic-op-rate bound): 16 lanes per edge, fp32
// gather + one red.global.add.v4.f32 per lane.
__global__ __launch_bounds__(256) void k_scatter(const int* __restrict__ ei,
                                                 float* __restrict__ out) {
    long long t = (long long)blockIdx.x * blockDim.x + threadIdx.x;
    int e  = (int)(t >> 4);
    int j4 = ((int)t & 15) * 4;
    if (e >= N_EDGES) return;

    int src = ei[e];
    int dst = ei[N_EDGES + e];
    float norm = g_dinv[src] * g_dinv[dst];

    float4 hv = *(const float4*)&g_h[(size_t)src * D + j4];
    float4 m = make_float4(hv.x * norm, hv.y * norm, hv.z * norm, hv.w * norm);

    float* p = &out[(size_t)dst * D + j4];
    asm volatile("red.global.add.v4.f32 [%0], {%1, %2, %3, %4};"
                 :: "l"(p), "f"(m.x), "f"(m.y), "f"(m.z), "f"(m.w)
                 : "memory");
}

// ---------------------------------------------------------------------------
extern "C" void kernel_launch(void* const* d_in, const int* in_sizes, int n_in,
                              void* d_out, int out_size) {
    const float* x  = (const float*)d_in[0];
    const int*   ei = (const int*)d_in[1];    // [2, E] int32
    const float* W  = (const float*)d_in[2];
    const float* b  = (const float*)d_in[3];
    float* out = (float*)d_out;

    (void)in_sizes; (void)n_in; (void)out_size;

    cudaFuncSetAttribute(k_fused, cudaFuncAttributeMaxDynamicSharedMemorySize,
                         FUSED_SMEM);

    void* deg_ptr = nullptr;
    cudaGetSymbolAddress(&deg_ptr, g_deg);
    cudaMemsetAsync(deg_ptr, 0, N_NODES * sizeof(int));

    k_fused<<<GEMM_BLOCKS + DEG_BLOCKS, 256, FUSED_SMEM>>>(x, W, ei);
    k_finish<<<(N_NODES * 16) / 256, 256>>>(b, out);

    long long scatter_threads = (long long)N_EDGES * 16;
    k_scatter<<<(unsigned)((scatter_threads + 255) / 256), 256>>>(ei, out);
}

// round 13
// speedup vs baseline: 3.2804x; 1.1839x over previous
#include <cuda_runtime.h>
#include <cuda_fp16.h>
#include <cuda_bf16.h>
#include <stdint.h>

// Problem constants (fixed by the dataset).
#define N_NODES 65536
#define N_EDGES 1048576
#define D 64

#define GEMM_BLOCKS    (N_NODES / 128)        // 512
#define DEG_BLOCKS     (N_EDGES / 4 / 256)    // 1024
#define BSUM_BLOCKS    64                     // 1024 nodes per block
#define REORDER_BLOCKS (N_EDGES / 256)        // 4096
#define SCALE_BLOCKS   (N_NODES * 16 / 256)   // 4096

// Scratch: __device__ globals (no allocation allowed in kernel_launch).
__device__ __align__(16) float  g_h[N_NODES * D];    // h = x @ W, fp32 (16 MB)
__device__ __align__(16) __half g_h16[N_NODES * D];  // h*dinv fp16 (8 MB)
__device__ float g_dinv[N_NODES];                    // rsqrt(deg+1)
__device__ __align__(16) int g_deg[N_NODES];         // in-degree w/o self-loop
__device__ int g_bsum[BSUM_BLOCKS];                  // per-chunk degree sums
__device__ __align__(16) int g_row_start[N_NODES + 4]; // CSR offsets (by dst)
__device__ __align__(16) int g_cursor[N_NODES];      // fill cursors
__device__ int g_csr_src[N_EDGES];                   // src per CSR slot

// ---------------------------------------------------------------------------
// Stage 1 (hetero): blocks [0,512) GEMM h = x @ W (R8-proven 128-row, 8x4);
// blocks [512,1536) degree count (hidden under the GEMM).
__global__ __launch_bounds__(256) void k_fused(const float* __restrict__ x,
                                               const float* __restrict__ W,
                                               const int* __restrict__ ei) {
    __shared__ __align__(16) float xs[64 * 128];
    __shared__ __align__(16) float ws[64 * 64];

    const int tid = threadIdx.x;

    if (blockIdx.x >= GEMM_BLOCKS) {
        int t = (blockIdx.x - GEMM_BLOCKS) * 256 + tid;
        int4 d = ((const int4*)(ei + N_EDGES))[t];
        atomicAdd(&g_deg[d.x], 1);
        atomicAdd(&g_deg[d.y], 1);
        atomicAdd(&g_deg[d.z], 1);
        atomicAdd(&g_deg[d.w], 1);
        return;
    }

    const int rowBase = blockIdx.x * 128;
    {
        const float4* Wv = (const float4*)W;
        float4* wsv = (float4*)ws;
        #pragma unroll
        for (int q = 0; q < 4; q++) wsv[tid + q * 256] = Wv[tid + q * 256];
    }
    {
        int row = tid & 127;
        int kq  = tid >> 7;
        const float4* xrow = (const float4*)&x[(size_t)(rowBase + row) * D];
        #pragma unroll
        for (int q = 0; q < 8; q++) {
            int k0 = kq * 32 + q * 4;
            float4 v = xrow[k0 >> 2];
            xs[(k0 + 0) * 128 + row] = v.x;
            xs[(k0 + 1) * 128 + row] = v.y;
            xs[(k0 + 2) * 128 + row] = v.z;
            xs[(k0 + 3) * 128 + row] = v.w;
        }
    }
    __syncthreads();

    const int ty = tid >> 4;
    const int tx = tid & 15;

    float acc[8][4] = {};
    #pragma unroll 8
    for (int k = 0; k < 64; k++) {
        float4 a0 = *(const float4*)&xs[k * 128 + ty * 8];
        float4 a1 = *(const float4*)&xs[k * 128 + ty * 8 + 4];
        float4 w4 = *(const float4*)&ws[k * 64 + tx * 4];
        float av[8] = {a0.x, a0.y, a0.z, a0.w, a1.x, a1.y, a1.z, a1.w};
        #pragma unroll
        for (int i = 0; i < 8; i++) {
            acc[i][0] += av[i] * w4.x;
            acc[i][1] += av[i] * w4.y;
            acc[i][2] += av[i] * w4.z;
            acc[i][3] += av[i] * w4.w;
        }
    }
    #pragma unroll
    for (int i = 0; i < 8; i++) {
        int r = rowBase + ty * 8 + i;
        *(float4*)&g_h[(size_t)r * D + tx * 4] =
            make_float4(acc[i][0], acc[i][1], acc[i][2], acc[i][3]);
    }
}

// ---------------------------------------------------------------------------
// Stage 2a: per-chunk degree sums (64 blocks x 1024 nodes). Fully parallel.
__global__ __launch_bounds__(256) void k_bsum() {
    __shared__ int red[256];
    int t = threadIdx.x;
    int4 v = ((const int4*)g_deg)[blockIdx.x * 256 + t];
    red[t] = v.x + v.y + v.z + v.w;
    __syncthreads();
    #pragma unroll
    for (int off = 128; off > 0; off >>= 1) {
        if (t < off) red[t] += red[t + off];
        __syncthreads();
    }
    if (t == 0) g_bsum[blockIdx.x] = red[0];
}

// Stage 2b: per-chunk exclusive scan -> row_start + cursor. 64 blocks.
__global__ __launch_bounds__(256) void k_offsets() {
    __shared__ int ts[256];
    __shared__ int base_s;
    const int t = threadIdx.x;
    const int blk = blockIdx.x;

    if (t == 0) {
        int bsum = 0;
        for (int j = 0; j < blk; j++) bsum += g_bsum[j];
        base_s = bsum;
    }
    int4 v = ((const int4*)g_deg)[blk * 256 + t];
    int s = v.x + v.y + v.z + v.w;
    ts[t] = s;
    __syncthreads();

    for (int off = 1; off < 256; off <<= 1) {
        int u = (t >= off) ? ts[t - off] : 0;
        __syncthreads();
        ts[t] += u;
        __syncthreads();
    }

    int r0 = base_s + ts[t] - s;   // exclusive prefix for this thread's 4 nodes
    int r1 = r0 + v.x;
    int r2 = r1 + v.y;
    int r3 = r2 + v.z;
    int node = blk * 1024 + t * 4;
    *(int4*)&g_row_start[node] = make_int4(r0, r1, r2, r3);
    *(int4*)&g_cursor[node]    = make_int4(r0, r1, r2, r3);
    if (blk == BSUM_BLOCKS - 1 && t == 255)
        g_row_start[N_NODES] = r3 + v.w;   // == N_EDGES
}

// ---------------------------------------------------------------------------
// Stage 3 (hetero): blocks [0,4096) reorder edges into CSR by dst;
// blocks [4096,8192) scale: dinv = rsqrt(deg+1); g_h16 = half(h * dinv).
__global__ __launch_bounds__(256) void k_prep(const int* __restrict__ ei) {
    const int tid = threadIdx.x;
    if (blockIdx.x < REORDER_BLOCKS) {
        int e = blockIdx.x * 256 + tid;
        int src = ei[e];
        int dst = ei[N_EDGES + e];
        int pos = atomicAdd(&g_cursor[dst], 1);
        g_csr_src[pos] = src;
    } else {
        int t = (blockIdx.x - REORDER_BLOCKS) * 256 + tid;
        int node = t >> 4;
        int j4   = (t & 15) * 4;
        float di = rsqrtf((float)(g_deg[node] + 1));
        if ((t & 15) == 0) g_dinv[node] = di;
        float4 hv = *(const float4*)&g_h[(size_t)node * D + j4];
        union { __half2 h2[2]; uint2 u; } pk;
        pk.h2[0] = __floats2half2_rn(hv.x * di, hv.y * di);
        pk.h2[1] = __floats2half2_rn(hv.z * di, hv.w * di);
        *(uint2*)&g_h16[(size_t)node * D + j4] = pk.u;
    }
}

// ---------------------------------------------------------------------------
// Stage 4: pull aggregation, warp per node, zero atomics.
// Indices loaded cooperatively (1 coalesced LDG per 32 neighbors), broadcast
// via shfl; each lane owns 2 features (coalesced 128B fp16 row gathers).
//   out[i] = b + dinv_i * sum_s (h[s]*dinv_s) + dinv_i^2 * h[i]
__global__ __launch_bounds__(256) void k_pull(const float* __restrict__ b,
                                              float* __restrict__ out) {
    const int node = (blockIdx.x * 256 + threadIdx.x) >> 5;
    const int lane = threadIdx.x & 31;

    int beg = g_row_start[node];
    int end = g_row_start[node + 1];

    float2 acc = make_float2(0.f, 0.f);
    for (int base = beg; base < end; base += 32) {
        int n = end - base;
        int m = n < 32 ? n : 32;
        int idx = (lane < m) ? g_csr_src[base + lane] : 0;
        for (int j = 0; j < m; j++) {
            int s = __shfl_sync(0xffffffffu, idx, j);
            uint32_t raw = *(const uint32_t*)&g_h16[(size_t)s * D + lane * 2];
            float2 f = __half22float2(*(__half2*)&raw);
            acc.x += f.x;
            acc.y += f.y;
        }
    }

    float di = g_dinv[node];
    float s2 = di * di;
    float2 hv = *(const float2*)&g_h[(size_t)node * D + lane * 2];
    float2 bv = *(const float2*)&b[lane * 2];
    *(float2*)&out[(size_t)node * D + lane * 2] =
        make_float2(bv.x + di * acc.x + s2 * hv.x,
                    bv.y + di * acc.y + s2 * hv.y);
}

// ---------------------------------------------------------------------------
extern "C" void kernel_launch(void* const* d_in, const int* in_sizes, int n_in,
                              void* d_out, int out_size) {
    const float* x  = (const float*)d_in[0];
    const int*   ei = (const int*)d_in[1];    // [2, E] int32
    const float* W  = (const float*)d_in[2];
    const float* b  = (const float*)d_in[3];
    float* out = (float*)d_out;

    (void)in_sizes; (void)n_in; (void)out_size;

    void* deg_ptr = nullptr;
    cudaGetSymbolAddress(&deg_ptr, g_deg);
    cudaMemsetAsync(deg_ptr, 0, N_NODES * sizeof(int));

    k_fused<<<GEMM_BLOCKS + DEG_BLOCKS, 256>>>(x, W, ei);
    k_bsum<<<BSUM_BLOCKS, 256>>>();
    k_offsets<<<BSUM_BLOCKS, 256>>>();
    k_prep<<<REORDER_BLOCKS + SCALE_BLOCKS, 256>>>(ei);
    k_pull<<<(N_NODES * 32) / 256, 256>>>(b, out);
}

// round 14
// speedup vs baseline: 3.3373x; 1.0173x over previous
#include <cuda_runtime.h>
#include <cuda_fp16.h>
#include <cuda_bf16.h>
#include <stdint.h>

// Problem constants (fixed by the dataset).
#define N_NODES 65536
#define N_EDGES 1048576
#define D 64

#define GEMM_BLOCKS    (N_NODES / 128)        // 512
#define DEG_BLOCKS     (N_EDGES / 4 / 256)    // 1024
#define BSUM_BLOCKS    64                     // 1024 nodes per block
#define REORDER_BLOCKS (N_EDGES / 4 / 256)    // 1024 (4 edges per thread)
#define SCALE_BLOCKS   (N_NODES * 16 / 256)   // 4096

// Scratch: __device__ globals (no allocation allowed in kernel_launch).
__device__ __align__(16) float  g_h[N_NODES * D];    // h = x @ W, fp32 (16 MB)
__device__ __align__(16) __half g_h16[N_NODES * D];  // h*dinv fp16 (8 MB)
__device__ float g_dinv[N_NODES];                    // rsqrt(deg+1)
__device__ __align__(16) int g_deg[N_NODES];         // in-degree w/o self-loop
__device__ int g_bsum[BSUM_BLOCKS];                  // per-chunk degree sums
__device__ __align__(16) int g_row_start[N_NODES + 4]; // CSR offsets (by dst)
__device__ __align__(16) int g_cursor[N_NODES];      // fill cursors
__device__ int g_csr_src[N_EDGES];                   // src per CSR slot

// ---------------------------------------------------------------------------
// Stage 1 (hetero): blocks [0,512) GEMM h = x @ W (proven 128-row, 8x4);
// blocks [512,1536) degree count (hidden under the GEMM).
__global__ __launch_bounds__(256) void k_fused(const float* __restrict__ x,
                                               const float* __restrict__ W,
                                               const int* __restrict__ ei) {
    __shared__ __align__(16) float xs[64 * 128];
    __shared__ __align__(16) float ws[64 * 64];

    const int tid = threadIdx.x;

    if (blockIdx.x >= GEMM_BLOCKS) {
        int t = (blockIdx.x - GEMM_BLOCKS) * 256 + tid;
        int4 d = ((const int4*)(ei + N_EDGES))[t];
        atomicAdd(&g_deg[d.x], 1);
        atomicAdd(&g_deg[d.y], 1);
        atomicAdd(&g_deg[d.z], 1);
        atomicAdd(&g_deg[d.w], 1);
        return;
    }

    const int rowBase = blockIdx.x * 128;
    {
        const float4* Wv = (const float4*)W;
        float4* wsv = (float4*)ws;
        #pragma unroll
        for (int q = 0; q < 4; q++) wsv[tid + q * 256] = Wv[tid + q * 256];
    }
    {
        int row = tid & 127;
        int kq  = tid >> 7;
        const float4* xrow = (const float4*)&x[(size_t)(rowBase + row) * D];
        #pragma unroll
        for (int q = 0; q < 8; q++) {
            int k0 = kq * 32 + q * 4;
            float4 v = xrow[k0 >> 2];
            xs[(k0 + 0) * 128 + row] = v.x;
            xs[(k0 + 1) * 128 + row] = v.y;
            xs[(k0 + 2) * 128 + row] = v.z;
            xs[(k0 + 3) * 128 + row] = v.w;
        }
    }
    __syncthreads();

    const int ty = tid >> 4;
    const int tx = tid & 15;

    float acc[8][4] = {};
    #pragma unroll 8
    for (int k = 0; k < 64; k++) {
        float4 a0 = *(const float4*)&xs[k * 128 + ty * 8];
        float4 a1 = *(const float4*)&xs[k * 128 + ty * 8 + 4];
        float4 w4 = *(const float4*)&ws[k * 64 + tx * 4];
        float av[8] = {a0.x, a0.y, a0.z, a0.w, a1.x, a1.y, a1.z, a1.w};
        #pragma unroll
        for (int i = 0; i < 8; i++) {
            acc[i][0] += av[i] * w4.x;
            acc[i][1] += av[i] * w4.y;
            acc[i][2] += av[i] * w4.z;
            acc[i][3] += av[i] * w4.w;
        }
    }
    #pragma unroll
    for (int i = 0; i < 8; i++) {
        int r = rowBase + ty * 8 + i;
        *(float4*)&g_h[(size_t)r * D + tx * 4] =
            make_float4(acc[i][0], acc[i][1], acc[i][2], acc[i][3]);
    }
}

// ---------------------------------------------------------------------------
// Stage 2a: per-chunk degree sums (64 blocks x 1024 nodes). Fully parallel.
__global__ __launch_bounds__(256) void k_bsum() {
    __shared__ int red[256];
    int t = threadIdx.x;
    int4 v = ((const int4*)g_deg)[blockIdx.x * 256 + t];
    red[t] = v.x + v.y + v.z + v.w;
    __syncthreads();
    #pragma unroll
    for (int off = 128; off > 0; off >>= 1) {
        if (t < off) red[t] += red[t + off];
        __syncthreads();
    }
    if (t == 0) g_bsum[blockIdx.x] = red[0];
}

// Stage 2b: per-chunk exclusive scan -> row_start + cursor. 64 blocks.
__global__ __launch_bounds__(256) void k_offsets() {
    __shared__ int ts[256];
    __shared__ int base_s;
    const int t = threadIdx.x;
    const int blk = blockIdx.x;

    if (t == 0) {
        int bsum = 0;
        for (int j = 0; j < blk; j++) bsum += g_bsum[j];
        base_s = bsum;
    }
    int4 v = ((const int4*)g_deg)[blk * 256 + t];
    int s = v.x + v.y + v.z + v.w;
    ts[t] = s;
    __syncthreads();

    for (int off = 1; off < 256; off <<= 1) {
        int u = (t >= off) ? ts[t - off] : 0;
        __syncthreads();
        ts[t] += u;
        __syncthreads();
    }

    int r0 = base_s + ts[t] - s;
    int r1 = r0 + v.x;
    int r2 = r1 + v.y;
    int r3 = r2 + v.z;
    int node = blk * 1024 + t * 4;
    *(int4*)&g_row_start[node] = make_int4(r0, r1, r2, r3);
    *(int4*)&g_cursor[node]    = make_int4(r0, r1, r2, r3);
    if (blk == BSUM_BLOCKS - 1 && t == 255)
        g_row_start[N_NODES] = r3 + v.w;   // == N_EDGES
}

// ---------------------------------------------------------------------------
// Stage 3 (hetero): blocks [0,1024) reorder edges into CSR, 4 edges/thread
// (int4 loads -> 4 returning atomics in flight: latency/MLP);
// blocks [1024,5120) scale: dinv = rsqrt(deg+1); g_h16 = half(h * dinv).
__global__ __launch_bounds__(256) void k_prep(const int* __restrict__ ei) {
    const int tid = threadIdx.x;
    if (blockIdx.x < REORDER_BLOCKS) {
        int t = blockIdx.x * 256 + tid;
        int4 s = ((const int4*)ei)[t];
        int4 d = ((const int4*)(ei + N_EDGES))[t];
        int p0 = atomicAdd(&g_cursor[d.x], 1);
        int p1 = atomicAdd(&g_cursor[d.y], 1);
        int p2 = atomicAdd(&g_cursor[d.z], 1);
        int p3 = atomicAdd(&g_cursor[d.w], 1);
        g_csr_src[p0] = s.x;
        g_csr_src[p1] = s.y;
        g_csr_src[p2] = s.z;
        g_csr_src[p3] = s.w;
    } else {
        int t = (blockIdx.x - REORDER_BLOCKS) * 256 + tid;
        int node = t >> 4;
        int j4   = (t & 15) * 4;
        float di = rsqrtf((float)(g_deg[node] + 1));
        if ((t & 15) == 0) g_dinv[node] = di;
        float4 hv = *(const float4*)&g_h[(size_t)node * D + j4];
        union { __half2 h2[2]; uint2 u; } pk;
        pk.h2[0] = __floats2half2_rn(hv.x * di, hv.y * di);
        pk.h2[1] = __floats2half2_rn(hv.z * di, hv.w * di);
        *(uint2*)&g_h16[(size_t)node * D + j4] = pk.u;
    }
}

// ---------------------------------------------------------------------------
// Stage 4: pull aggregation, warp per node, zero atomics (proven R13).
__global__ __launch_bounds__(256) void k_pull(const float* __restrict__ b,
                                              float* __restrict__ out) {
    const int node = (blockIdx.x * 256 + threadIdx.x) >> 5;
    const int lane = threadIdx.x & 31;

    int beg = g_row_start[node];
    int end = g_row_start[node + 1];

    float2 acc = make_float2(0.f, 0.f);
    for (int base = beg; base < end; base += 32) {
        int n = end - base;
        int m = n < 32 ? n : 32;
        int idx = (lane < m) ? g_csr_src[base + lane] : 0;
        for (int j = 0; j < m; j++) {
            int s = __shfl_sync(0xffffffffu, idx, j);
            uint32_t raw = *(const uint32_t*)&g_h16[(size_t)s * D + lane * 2];
            float2 f = __half22float2(*(__half2*)&raw);
            acc.x += f.x;
            acc.y += f.y;
        }
    }

    float di = g_dinv[node];
    float s2 = di * di;
    float2 hv = *(const float2*)&g_h[(size_t)node * D + lane * 2];
    float2 bv = *(const float2*)&b[lane * 2];
    *(float2*)&out[(size_t)node * D + lane * 2] =
        make_float2(bv.x + di * acc.x + s2 * hv.x,
                    bv.y + di * acc.y + s2 * hv.y);
}

// ---------------------------------------------------------------------------
extern "C" void kernel_launch(void* const* d_in, const int* in_sizes, int n_in,
                              void* d_out, int out_size) {
    const float* x  = (const float*)d_in[0];
    const int*   ei = (const int*)d_in[1];    // [2, E] int32
    const float* W  = (const float*)d_in[2];
    const float* b  = (const float*)d_in[3];
    float* out = (float*)d_out;

    (void)in_sizes; (void)n_in; (void)out_size;

    void* deg_ptr = nullptr;
    cudaGetSymbolAddress(&deg_ptr, g_deg);
    cudaMemsetAsync(deg_ptr, 0, N_NODES * sizeof(int));

    k_fused<<<GEMM_BLOCKS + DEG_BLOCKS, 256>>>(x, W, ei);
    k_bsum<<<BSUM_BLOCKS, 256>>>();
    k_offsets<<<BSUM_BLOCKS, 256>>>();
    k_prep<<<REORDER_BLOCKS + SCALE_BLOCKS, 256>>>(ei);
    k_pull<<<(N_NODES * 32) / 256, 256>>>(b, out);
}